// round 4
// baseline (speedup 1.0000x reference)
#include <cuda_runtime.h>

typedef unsigned long long u64;

#define NR 128
#define SGN2 0x8000000080000000ULL

__device__ __forceinline__ u64 pk2(float lo, float hi) {
    u64 r; asm("mov.b64 %0, {%1,%2};" : "=l"(r) : "f"(lo), "f"(hi)); return r;
}
__device__ __forceinline__ void upk2(float& lo, float& hi, u64 v) {
    asm("mov.b64 {%0,%1}, %2;" : "=f"(lo), "=f"(hi) : "l"(v));
}
#define FMA2(d, a, b) asm("fma.rn.f32x2 %0, %1, %2, %0;" : "+l"(d) : "l"(a), "l"(b))
#define MUL2(d, a, b) asm("mul.rn.f32x2 %0, %1, %2;" : "=l"(d) : "l"(a), "l"(b))

#define TP(J, PR, K) FMA2(o2[J], PR, wn2[K]);
#define TN(J, PR, K) { u64 _n = (PR) ^ SGN2; FMA2(o2[J], _n, wn2[K]); }

__device__ __forceinline__ void normalize8(const float* ww,
                                           float s0, float s1, float s2, float s3,
                                           float* wn) {
    float nrm0 = fabsf(ww[0]);
    float nrm1 = __fsqrt_rn(ww[1]*ww[1] + ww[2]*ww[2] + ww[3]*ww[3]);
    float nrm2 = __fsqrt_rn(ww[4]*ww[4] + ww[5]*ww[5] + ww[6]*ww[6]);
    float nrm3 = fabsf(ww[7]);
    float r0 = __fdividef(1.0f, fmaf(s0, nrm0 - 1.0f, 1.0f));
    float r1 = __fdividef(1.0f, fmaf(s1, nrm1 - 1.0f, 1.0f));
    float r2 = __fdividef(1.0f, fmaf(s2, nrm2 - 1.0f, 1.0f));
    float r3 = __fdividef(1.0f, fmaf(s3, nrm3 - 1.0f, 1.0f));
    wn[0] = ww[0] * r0;
    wn[1] = ww[1] * r1;  wn[2] = ww[2] * r1;  wn[3] = ww[3] * r1;
    wn[4] = ww[4] * r2;  wn[5] = ww[5] * r2;  wn[6] = ww[6] * r2;
    wn[7] = ww[7] * r3;
}

__global__ __launch_bounds__(NR) void mv_gp_kernel(
    const float* __restrict__ v,
    const float* __restrict__ w,
    const float* __restrict__ weight,
    const float* __restrict__ a,
    float* __restrict__ out,
    int B, int F)
{
    __shared__ float wt_s[20][NR];   // transposed weight rows

    const int tid = threadIdx.x;
    const int n0  = blockIdx.x * NR;

    // ---- stage weight rows (coalesced float4 -> transposed smem) ----
    {
        const float4* wsrc = (const float4*)(weight + (size_t)n0 * 20);
        for (int i = tid; i < (NR * 20) / 4; i += NR) {
            float4 x = wsrc[i];
            int e = i * 4;
            wt_s[(e + 0) % 20][(e + 0) / 20] = x.x;
            wt_s[(e + 1) % 20][(e + 1) / 20] = x.y;
            wt_s[(e + 2) % 20][(e + 2) / 20] = x.z;
            wt_s[(e + 3) % 20][(e + 3) / 20] = x.w;
        }
    }

    const int n = n0 + tid;

    // sigmoid(a[n]) — coalesced per-thread float4
    const float4 a4 = *(const float4*)(a + (size_t)n * 4);
    const float s0 = __fdividef(1.0f, 1.0f + __expf(-a4.x));
    const float s1 = __fdividef(1.0f, 1.0f + __expf(-a4.y));
    const float s2 = __fdividef(1.0f, 1.0f + __expf(-a4.z));
    const float s3 = __fdividef(1.0f, 1.0f + __expf(-a4.w));

    __syncthreads();

    // packed per-feature weights (both halves equal)
    u64 wt2[20];
#pragma unroll
    for (int p = 0; p < 20; ++p) {
        float x = wt_s[p][tid];
        wt2[p] = pk2(x, x);
    }

    // ---- two batch rows per thread, packed lanes ----
    const int b0 = blockIdx.y * 2;
    const size_t siteA = (size_t)b0 * F + n;
    const size_t siteB = (b0 + 1 < B) ? siteA + (size_t)F : siteA;

    const float4* vA4 = (const float4*)(v + siteA * 8);
    const float4* wA4 = (const float4*)(w + siteA * 8);
    const float4* vB4 = (const float4*)(v + siteB * 8);
    const float4* wB4 = (const float4*)(w + siteB * 8);
    float4 va0 = vA4[0], va1 = vA4[1];
    float4 wa0 = wA4[0], wa1 = wA4[1];
    float4 vb0 = vB4[0], vb1 = vB4[1];
    float4 wb0 = wB4[0], wb1 = wB4[1];

    float viA[8] = {va0.x, va0.y, va0.z, va0.w, va1.x, va1.y, va1.z, va1.w};
    float wwA[8] = {wa0.x, wa0.y, wa0.z, wa0.w, wa1.x, wa1.y, wa1.z, wa1.w};
    float viB[8] = {vb0.x, vb0.y, vb0.z, vb0.w, vb1.x, vb1.y, vb1.z, vb1.w};
    float wwB[8] = {wb0.x, wb0.y, wb0.z, wb0.w, wb1.x, wb1.y, wb1.z, wb1.w};

    float wnA[8], wnB[8];
    normalize8(wwA, s0, s1, s2, s3, wnA);
    normalize8(wwB, s0, s1, s2, s3, wnB);

    u64 vi2[8], wn2[8];
#pragma unroll
    for (int t = 0; t < 8; ++t) {
        vi2[t] = pk2(viA[t], viB[t]);
        wn2[t] = pk2(wnA[t], wnB[t]);
    }

    u64 o2[8] = {0, 0, 0, 0, 0, 0, 0, 0};

    // ---- 64-term bilinear form, packed over 2 sites ----
    // i = 0 (scalar)
    {
        u64 p0, p1, p2, p3;
        MUL2(p0, wt2[0], vi2[0]); MUL2(p1, wt2[1], vi2[0]);
        MUL2(p2, wt2[2], vi2[0]); MUL2(p3, wt2[3], vi2[0]);
        TP(0,p0,0) TP(1,p1,1) TP(2,p1,2) TP(3,p1,3)
        TP(4,p2,4) TP(5,p2,5) TP(6,p2,6) TP(7,p3,7)
    }
    // i = 1 (e1)
    {
        u64 p4,p5,p6,p7,p8,p9;
        MUL2(p4,wt2[4],vi2[1]); MUL2(p5,wt2[5],vi2[1]); MUL2(p6,wt2[6],vi2[1]);
        MUL2(p7,wt2[7],vi2[1]); MUL2(p8,wt2[8],vi2[1]); MUL2(p9,wt2[9],vi2[1]);
        TP(1,p5,0) TP(0,p4,1) TP(4,p7,2) TP(5,p7,3)
        TP(2,p6,4) TP(3,p6,5) TP(7,p9,6) TP(6,p8,7)
    }
    // i = 2 (e2)
    {
        u64 p4,p5,p6,p7,p8,p9;
        MUL2(p4,wt2[4],vi2[2]); MUL2(p5,wt2[5],vi2[2]); MUL2(p6,wt2[6],vi2[2]);
        MUL2(p7,wt2[7],vi2[2]); MUL2(p8,wt2[8],vi2[2]); MUL2(p9,wt2[9],vi2[2]);
        TP(2,p5,0) TN(4,p7,1) TP(0,p4,2) TP(6,p7,3)
        TN(1,p6,4) TN(7,p9,5) TP(3,p6,6) TN(5,p8,7)
    }
    // i = 3 (e3)
    {
        u64 p4,p5,p6,p7,p8,p9;
        MUL2(p4,wt2[4],vi2[3]); MUL2(p5,wt2[5],vi2[3]); MUL2(p6,wt2[6],vi2[3]);
        MUL2(p7,wt2[7],vi2[3]); MUL2(p8,wt2[8],vi2[3]); MUL2(p9,wt2[9],vi2[3]);
        TP(3,p5,0) TN(5,p7,1) TN(6,p7,2) TP(0,p4,3)
        TP(7,p9,4) TN(1,p6,5) TN(2,p6,6) TP(4,p8,7)
    }
    // i = 4 (e12)
    {
        u64 p10,p11,p12,p13,p14,p15;
        MUL2(p10,wt2[10],vi2[4]); MUL2(p11,wt2[11],vi2[4]); MUL2(p12,wt2[12],vi2[4]);
        MUL2(p13,wt2[13],vi2[4]); MUL2(p14,wt2[14],vi2[4]); MUL2(p15,wt2[15],vi2[4]);
        TN(4,p13,0) TP(2,p11,1) TN(1,p11,2) TN(7,p15,3)
        TP(0,p10,4) TP(6,p14,5) TN(5,p14,6) TP(3,p12,7)
    }
    // i = 5 (e13)
    {
        u64 p10,p11,p12,p13,p14,p15;
        MUL2(p10,wt2[10],vi2[5]); MUL2(p11,wt2[11],vi2[5]); MUL2(p12,wt2[12],vi2[5]);
        MUL2(p13,wt2[13],vi2[5]); MUL2(p14,wt2[14],vi2[5]); MUL2(p15,wt2[15],vi2[5]);
        TN(5,p13,0) TP(3,p11,1) TP(7,p15,2) TN(1,p11,3)
        TN(6,p14,4) TP(0,p10,5) TP(4,p14,6) TN(2,p12,7)
    }
    // i = 6 (e23)
    {
        u64 p10,p11,p12,p13,p14,p15;
        MUL2(p10,wt2[10],vi2[6]); MUL2(p11,wt2[11],vi2[6]); MUL2(p12,wt2[12],vi2[6]);
        MUL2(p13,wt2[13],vi2[6]); MUL2(p14,wt2[14],vi2[6]); MUL2(p15,wt2[15],vi2[6]);
        TN(6,p13,0) TN(7,p15,1) TP(3,p11,2) TN(2,p11,3)
        TP(5,p14,4) TN(4,p14,5) TP(0,p10,6) TP(1,p12,7)
    }
    // i = 7 (e123)
    {
        u64 p16,p17,p18,p19;
        MUL2(p16,wt2[16],vi2[7]); MUL2(p17,wt2[17],vi2[7]);
        MUL2(p18,wt2[18],vi2[7]); MUL2(p19,wt2[19],vi2[7]);
        TN(7,p19,0) TN(6,p18,1) TP(5,p18,2) TN(4,p18,3)
        TP(3,p17,4) TN(2,p17,5) TP(1,p17,6) TP(0,p16,7)
    }

    // ---- unpack + store ----
    float oA[8], oB[8];
#pragma unroll
    for (int t = 0; t < 8; ++t) upk2(oA[t], oB[t], o2[t]);

    float4* oA4 = (float4*)(out + siteA * 8);
    oA4[0] = make_float4(oA[0], oA[1], oA[2], oA[3]);
    oA4[1] = make_float4(oA[4], oA[5], oA[6], oA[7]);
    float4* oB4 = (float4*)(out + siteB * 8);
    oB4[0] = make_float4(oB[0], oB[1], oB[2], oB[3]);
    oB4[1] = make_float4(oB[4], oB[5], oB[6], oB[7]);
}

extern "C" void kernel_launch(void* const* d_in, const int* in_sizes, int n_in,
                              void* d_out, int out_size) {
    const float* v      = (const float*)d_in[0];
    const float* w      = (const float*)d_in[1];
    const float* weight = (const float*)d_in[2];
    const float* a      = (const float*)d_in[3];
    float* out = (float*)d_out;

    int F     = in_sizes[3] / 4;        // a is [F, 4]
    int total = in_sizes[0] / 8;        // B * F
    int B     = total / F;

    dim3 grid(F / NR, (B + 1) / 2);
    mv_gp_kernel<<<grid, NR>>>(v, w, weight, a, out, B, F);
}

// round 7
// speedup vs baseline: 1.1150x; 1.1150x over previous
#include <cuda_runtime.h>

// MVGeometricProduct — latency/tail-bound fix round (3rd submit; prior two runs infra-failed).
// Block = 256 threads = 256 features; U=2 batch rows per thread.
// grid = (F/256, B/2) = (3, 512) = 1536 blocks (~3.5 waves -> small tail).
// All 8 LDG.128 issued before compute (MLP 8). Weight smem row-major, pad 21
// (conflict-free per-thread row reads).

#define NR 256
#define PADW 21

__device__ __forceinline__ void normalize8(const float* ww,
                                           float s0, float s1, float s2, float s3,
                                           float* wn) {
    float nrm0 = fabsf(ww[0]);
    float nrm1 = __fsqrt_rn(ww[1]*ww[1] + ww[2]*ww[2] + ww[3]*ww[3]);
    float nrm2 = __fsqrt_rn(ww[4]*ww[4] + ww[5]*ww[5] + ww[6]*ww[6]);
    float nrm3 = fabsf(ww[7]);
    float r0 = __fdividef(1.0f, fmaf(s0, nrm0 - 1.0f, 1.0f));
    float r1 = __fdividef(1.0f, fmaf(s1, nrm1 - 1.0f, 1.0f));
    float r2 = __fdividef(1.0f, fmaf(s2, nrm2 - 1.0f, 1.0f));
    float r3 = __fdividef(1.0f, fmaf(s3, nrm3 - 1.0f, 1.0f));
    wn[0] = ww[0] * r0;
    wn[1] = ww[1] * r1;  wn[2] = ww[2] * r1;  wn[3] = ww[3] * r1;
    wn[4] = ww[4] * r2;  wn[5] = ww[5] * r2;  wn[6] = ww[6] * r2;
    wn[7] = ww[7] * r3;
}

__device__ __forceinline__ void site_compute(const float* vi, const float* wn,
                                             const float* wt, float* o) {
#pragma unroll
    for (int t = 0; t < 8; ++t) o[t] = 0.0f;
#define T(I, K, J, S, P) o[J] = fmaf((S) * wt[P] * vi[I], wn[K], o[J]);
    // i = 0 (scalar)
    T(0,0,0, 1.f, 0)  T(0,1,1, 1.f, 1)  T(0,2,2, 1.f, 1)  T(0,3,3, 1.f, 1)
    T(0,4,4, 1.f, 2)  T(0,5,5, 1.f, 2)  T(0,6,6, 1.f, 2)  T(0,7,7, 1.f, 3)
    // i = 1 (e1)
    T(1,0,1, 1.f, 5)  T(1,1,0, 1.f, 4)  T(1,2,4, 1.f, 7)  T(1,3,5, 1.f, 7)
    T(1,4,2, 1.f, 6)  T(1,5,3, 1.f, 6)  T(1,6,7, 1.f, 9)  T(1,7,6, 1.f, 8)
    // i = 2 (e2)
    T(2,0,2, 1.f, 5)  T(2,1,4,-1.f, 7)  T(2,2,0, 1.f, 4)  T(2,3,6, 1.f, 7)
    T(2,4,1,-1.f, 6)  T(2,5,7,-1.f, 9)  T(2,6,3, 1.f, 6)  T(2,7,5,-1.f, 8)
    // i = 3 (e3)
    T(3,0,3, 1.f, 5)  T(3,1,5,-1.f, 7)  T(3,2,6,-1.f, 7)  T(3,3,0, 1.f, 4)
    T(3,4,7, 1.f, 9)  T(3,5,1,-1.f, 6)  T(3,6,2,-1.f, 6)  T(3,7,4, 1.f, 8)
    // i = 4 (e12)
    T(4,0,4,-1.f,13)  T(4,1,2, 1.f,11)  T(4,2,1,-1.f,11)  T(4,3,7,-1.f,15)
    T(4,4,0, 1.f,10)  T(4,5,6, 1.f,14)  T(4,6,5,-1.f,14)  T(4,7,3, 1.f,12)
    // i = 5 (e13)
    T(5,0,5,-1.f,13)  T(5,1,3, 1.f,11)  T(5,2,7, 1.f,15)  T(5,3,1,-1.f,11)
    T(5,4,6,-1.f,14)  T(5,5,0, 1.f,10)  T(5,6,4, 1.f,14)  T(5,7,2,-1.f,12)
    // i = 6 (e23)
    T(6,0,6,-1.f,13)  T(6,1,7,-1.f,15)  T(6,2,3, 1.f,11)  T(6,3,2,-1.f,11)
    T(6,4,5, 1.f,14)  T(6,5,4,-1.f,14)  T(6,6,0, 1.f,10)  T(6,7,1, 1.f,12)
    // i = 7 (e123)
    T(7,0,7,-1.f,19)  T(7,1,6,-1.f,18)  T(7,2,5, 1.f,18)  T(7,3,4,-1.f,18)
    T(7,4,3, 1.f,17)  T(7,5,2,-1.f,17)  T(7,6,1, 1.f,17)  T(7,7,0, 1.f,16)
#undef T
}

__global__ __launch_bounds__(NR) void mv_gp_kernel(
    const float* __restrict__ v,
    const float* __restrict__ w,
    const float* __restrict__ weight,
    const float* __restrict__ a,
    float* __restrict__ out,
    int B, int F)
{
    __shared__ float wt_s[NR * PADW];   // row-major, padded (gcd(21,32)=1)

    const int tid = threadIdx.x;
    const int n0  = blockIdx.x * NR;

    // ---- stage weight rows: coalesced float4 reads, scalar padded writes ----
    {
        const float4* wsrc = (const float4*)(weight + (size_t)n0 * 20);
#pragma unroll
        for (int it = 0; it < 5; ++it) {
            int i = tid + it * NR;          // 1280 float4 total
            float4 x = wsrc[i];
            int e = i * 4;
            int base = (e / 20) * PADW + (e % 20);
            wt_s[base + 0] = x.x;
            wt_s[base + 1] = x.y;
            wt_s[base + 2] = x.z;
            wt_s[base + 3] = x.w;
        }
    }

    const int n = n0 + tid;

    // sigmoid(a[n]) — coalesced float4 per thread
    const float4 a4 = *(const float4*)(a + (size_t)n * 4);
    const float s0 = __fdividef(1.0f, 1.0f + __expf(-a4.x));
    const float s1 = __fdividef(1.0f, 1.0f + __expf(-a4.y));
    const float s2 = __fdividef(1.0f, 1.0f + __expf(-a4.z));
    const float s3 = __fdividef(1.0f, 1.0f + __expf(-a4.w));

    __syncthreads();

    // per-thread weight row from smem (conflict-free: stride 21)
    float wt[20];
    const float* wrow = &wt_s[tid * PADW];
#pragma unroll
    for (int p = 0; p < 20; ++p) wt[p] = wrow[p];

    // ---- two batch rows per thread; all 8 LDG.128 before compute ----
    const int b0 = blockIdx.y * 2;
    const size_t siteA = (size_t)b0 * F + n;
    const size_t siteB = (b0 + 1 < B) ? siteA + (size_t)F : siteA;

    const float4* vA4 = (const float4*)(v + siteA * 8);
    const float4* wA4 = (const float4*)(w + siteA * 8);
    const float4* vB4 = (const float4*)(v + siteB * 8);
    const float4* wB4 = (const float4*)(w + siteB * 8);

    float4 va0 = vA4[0], va1 = vA4[1];
    float4 wa0 = wA4[0], wa1 = wA4[1];
    float4 vb0 = vB4[0], vb1 = vB4[1];
    float4 wb0 = wB4[0], wb1 = wB4[1];

    // ---- site A ----
    {
        float vi[8] = {va0.x, va0.y, va0.z, va0.w, va1.x, va1.y, va1.z, va1.w};
        float ww[8] = {wa0.x, wa0.y, wa0.z, wa0.w, wa1.x, wa1.y, wa1.z, wa1.w};
        float wn[8], o[8];
        normalize8(ww, s0, s1, s2, s3, wn);
        site_compute(vi, wn, wt, o);
        float4* o4 = (float4*)(out + siteA * 8);
        o4[0] = make_float4(o[0], o[1], o[2], o[3]);
        o4[1] = make_float4(o[4], o[5], o[6], o[7]);
    }
    // ---- site B ----
    {
        float vi[8] = {vb0.x, vb0.y, vb0.z, vb0.w, vb1.x, vb1.y, vb1.z, vb1.w};
        float ww[8] = {wb0.x, wb0.y, wb0.z, wb0.w, wb1.x, wb1.y, wb1.z, wb1.w};
        float wn[8], o[8];
        normalize8(ww, s0, s1, s2, s3, wn);
        site_compute(vi, wn, wt, o);
        float4* o4 = (float4*)(out + siteB * 8);
        o4[0] = make_float4(o[0], o[1], o[2], o[3]);
        o4[1] = make_float4(o[4], o[5], o[6], o[7]);
    }
}

extern "C" void kernel_launch(void* const* d_in, const int* in_sizes, int n_in,
                              void* d_out, int out_size) {
    const float* v      = (const float*)d_in[0];
    const float* w      = (const float*)d_in[1];
    const float* weight = (const float*)d_in[2];
    const float* a      = (const float*)d_in[3];
    float* out = (float*)d_out;

    int F     = in_sizes[3] / 4;        // a is [F, 4]
    int total = in_sizes[0] / 8;        // B * F
    int B     = total / F;

    dim3 grid(F / NR, (B + 1) / 2);
    mv_gp_kernel<<<grid, NR>>>(v, w, weight, a, out, B, F);
}